// round 3
// baseline (speedup 1.0000x reference)
#include <cuda_runtime.h>
#include <math.h>

#define BATCH 256
#define SEQ   512
#define INP   300
#define HID   128
#define G3    384   // 3*HID, PyTorch gate order: [reset; update; new]

// Scratch for input-to-gate preactivations (includes b_ih): [B, T, 3H] fp32
__device__ float g_xg[(size_t)BATCH * SEQ * G3];

// ---------------------------------------------------------------------------
// Kernel 1: xg[m, g] = sum_k x[m, k] * W_ih[g, k] + b_ih[g]
//   M = BATCH*SEQ = 131072, N = 384, K = 300
//   Tiled SGEMM: BM=128, BN=64, BK=8, 256 threads, 8x4 micro-tile per thread.
// ---------------------------------------------------------------------------
#define BM 128
#define BN 64
#define BK 8
#define TM 8
#define TN 4

__global__ __launch_bounds__(256) void proj_kernel(const float* __restrict__ x,
                                                   const float* __restrict__ W,
                                                   const float* __restrict__ bih) {
    __shared__ __align__(16) float As[BK][BM];   // A tile, k-major (transposed)
    __shared__ __align__(16) float Bs[BK][BN];   // B tile, k-major

    const int tid = threadIdx.x;
    const int tx  = tid & 15;    // n direction (16 * TN = 64)
    const int ty  = tid >> 4;    // m direction (16 * TM = 128)
    const int bn0 = blockIdx.x * BN;
    const int bm0 = blockIdx.y * BM;

    float acc[TM][TN];
    #pragma unroll
    for (int i = 0; i < TM; i++)
        #pragma unroll
        for (int j = 0; j < TN; j++) acc[i][j] = 0.f;

    const int KT = (INP + BK - 1) / BK;  // 38 iterations, last one zero-padded
    for (int it = 0; it < KT; it++) {
        const int k0 = it * BK;

        // Load A tile: 128x8 = 1024 elems, 4 per thread (coalesced over k then m)
        #pragma unroll
        for (int l = 0; l < 4; l++) {
            int e  = tid + l * 256;
            int m  = e >> 3;
            int kk = e & 7;
            float v = (k0 + kk < INP) ? x[(size_t)(bm0 + m) * INP + k0 + kk] : 0.f;
            As[kk][m] = v;
        }
        // Load B tile: 64x8 = 512 elems, 2 per thread
        #pragma unroll
        for (int l = 0; l < 2; l++) {
            int e  = tid + l * 256;
            int n  = e >> 3;
            int kk = e & 7;
            float v = (k0 + kk < INP) ? W[(size_t)(bn0 + n) * INP + k0 + kk] : 0.f;
            Bs[kk][n] = v;
        }
        __syncthreads();

        #pragma unroll
        for (int kk = 0; kk < BK; kk++) {
            float4 av0 = *((const float4*)&As[kk][ty * TM]);
            float4 av1 = *((const float4*)&As[kk][ty * TM + 4]);
            float4 bv  = *((const float4*)&Bs[kk][tx * TN]);
            float a[TM] = {av0.x, av0.y, av0.z, av0.w, av1.x, av1.y, av1.z, av1.w};
            float bb[TN] = {bv.x, bv.y, bv.z, bv.w};
            #pragma unroll
            for (int i = 0; i < TM; i++)
                #pragma unroll
                for (int j = 0; j < TN; j++)
                    acc[i][j] = fmaf(a[i], bb[j], acc[i][j]);
        }
        __syncthreads();
    }

    // Epilogue: add b_ih, vectorized store
    float4 bi = *((const float4*)&bih[bn0 + tx * TN]);
    #pragma unroll
    for (int i = 0; i < TM; i++) {
        size_t m = (size_t)bm0 + ty * TM + i;
        float4 o;
        o.x = acc[i][0] + bi.x;
        o.y = acc[i][1] + bi.y;
        o.z = acc[i][2] + bi.z;
        o.w = acc[i][3] + bi.w;
        *((float4*)&g_xg[m * G3 + bn0 + tx * TN]) = o;
    }
}

// ---------------------------------------------------------------------------
// Kernel 2: persistent GRU recurrence, one CTA per batch row (rows independent).
//   384 threads; thread g owns W_hh row g in 128 registers.
//   Per step: hg[g] = dot(W_hh[g], h) + b_hh[g]  (h broadcast from smem),
//   then threads 0..127 apply the gate math. Classifier fused in the tail.
// ---------------------------------------------------------------------------
__global__ __launch_bounds__(384) void gru_kernel(const float* __restrict__ W_hh,
                                                  const float* __restrict__ b_hh,
                                                  const float* __restrict__ W_out,
                                                  const float* __restrict__ b_out,
                                                  float* __restrict__ out) {
    __shared__ __align__(16) float h_s[HID];
    __shared__ float hgs[G3];
    __shared__ float xgs[G3];
    __shared__ float feat[HID];

    const int g = threadIdx.x;
    const int b = blockIdx.x;

    // Cache W_hh row g in registers (one-time; row is L1/L2 resident)
    float w[HID];
    const float* wr = W_hh + g * HID;
    #pragma unroll
    for (int i = 0; i < HID; i++) w[i] = wr[i];
    const float bh = b_hh[g];

    if (g < HID) h_s[g] = 0.f;
    __syncthreads();

    const float* xp = g_xg + (size_t)b * SEQ * G3 + g;
    float xg_next = xp[0];

    for (int t = 0; t < SEQ; t++) {
        const float xv = xg_next;
        if (t + 1 < SEQ) xg_next = xp[(size_t)(t + 1) * G3];  // prefetch next step

        // hg = dot(w, h) with 4 accumulators; h read as broadcast float4 LDS
        float a0 = 0.f, a1 = 0.f, a2 = 0.f, a3 = 0.f;
        const float4* h4 = (const float4*)h_s;
        #pragma unroll
        for (int k = 0; k < HID / 4; k++) {
            float4 hv = h4[k];
            a0 = fmaf(w[4 * k + 0], hv.x, a0);
            a1 = fmaf(w[4 * k + 1], hv.y, a1);
            a2 = fmaf(w[4 * k + 2], hv.z, a2);
            a3 = fmaf(w[4 * k + 3], hv.w, a3);
        }
        hgs[g] = (a0 + a1) + (a2 + a3) + bh;
        xgs[g] = xv;
        __syncthreads();   // all dots done reading h_s; hgs/xgs visible

        if (g < HID) {
            float r  = 1.f / (1.f + __expf(-(xgs[g] + hgs[g])));
            float z  = 1.f / (1.f + __expf(-(xgs[g + HID] + hgs[g + HID])));
            float n  = tanhf(xgs[g + 2 * HID] + r * hgs[g + 2 * HID]);
            float hn = (1.f - z) * n + z * h_s[g];
            h_s[g] = hn;   // only thread g touches h_s[g] in this window
        }
        __syncthreads();   // new h visible before next step's dots
    }

    // ---- fused classifier: relu -> linear(2) -> log_softmax ----
    if (g < HID) feat[g] = fmaxf(h_s[g], 0.f);
    __syncthreads();
    if (g < 2) {
        const float* wo = W_out + g * HID;
        float s = 0.f;
        #pragma unroll
        for (int j = 0; j < HID; j++) s = fmaf(wo[j], feat[j], s);
        hgs[g] = s + b_out[g];
    }
    __syncthreads();
    if (g == 0) {
        float l0 = hgs[0], l1 = hgs[1];
        float mx = fmaxf(l0, l1);
        float lse = mx + logf(expf(l0 - mx) + expf(l1 - mx));
        out[b * 2 + 0] = l0 - lse;
        out[b * 2 + 1] = l1 - lse;
    }
}

// ---------------------------------------------------------------------------
// Launch: inputs per metadata order: x, W_ih, W_hh, b_ih, b_hh, W_out, b_out
// ---------------------------------------------------------------------------
extern "C" void kernel_launch(void* const* d_in, const int* in_sizes, int n_in,
                              void* d_out, int out_size) {
    const float* x     = (const float*)d_in[0];
    const float* W_ih  = (const float*)d_in[1];
    const float* W_hh  = (const float*)d_in[2];
    const float* b_ih  = (const float*)d_in[3];
    const float* b_hh  = (const float*)d_in[4];
    const float* W_out = (const float*)d_in[5];
    const float* b_out = (const float*)d_in[6];
    float* out = (float*)d_out;

    dim3 pgrid(G3 / BN, (BATCH * SEQ) / BM);   // 6 x 1024
    proj_kernel<<<pgrid, 256>>>(x, W_ih, b_ih);
    gru_kernel<<<BATCH, 384>>>(W_hh, b_hh, W_out, b_out, out);
}